// round 1
// baseline (speedup 1.0000x reference)
#include <cuda_runtime.h>
#include <cuda_bf16.h>
#include <math.h>

// Problem constants
#define B_ 128
#define T_ 256
#define E_ 384
#define H_ 6
#define HS_ 64
#define L_ 6
#define V_ 78
#define FF_ 1536
#define QKV3_ 192           // 3*HS per head
#define NQKV_ (H_ * QKV3_)  // 1152

#define BT_ (B_ * T_)       // 32768

// ---------------- device scratch (static, no allocations) ----------------
__device__ float g_x   [BT_ * E_];        // residual stream
__device__ float g_xn  [BT_ * E_];        // layernorm output
__device__ float g_qkv [BT_ * NQKV_];     // [B,T,H,192]
__device__ float g_obuf[BT_ * E_];        // attention output (reshaped)
__device__ float g_ff  [BT_ * FF_];       // hidden FF activations
__device__ float g_wq  [L_ * E_ * NQKV_]; // repacked qkv weights [L,E,H*192]

// ---------------- embedding ----------------
__global__ void embed_kernel(const int* __restrict__ ctx,
                             const float* __restrict__ tok,
                             const float* __restrict__ pos,
                             float* __restrict__ x) {
    int i = blockIdx.x * blockDim.x + threadIdx.x;
    if (i >= BT_ * E_) return;
    int e  = i % E_;
    int bt = i / E_;
    int t  = bt % T_;
    x[i] = tok[ctx[bt] * E_ + e] + pos[t * E_ + e];
}

// ---------------- repack w_qkv [L,H,E,192] -> [L,E,H*192] ----------------
__global__ void repack_kernel(const float* __restrict__ w, float* __restrict__ wp) {
    int i = blockIdx.x * blockDim.x + threadIdx.x;
    if (i >= L_ * H_ * E_ * QKV3_) return;
    int f = i % QKV3_;
    int e = (i / QKV3_) % E_;
    int h = (i / (QKV3_ * E_)) % H_;
    int l = i / (QKV3_ * E_ * H_);
    wp[((size_t)l * E_ + e) * NQKV_ + h * QKV3_ + f] = w[i];
}

// ---------------- layernorm: one block per token, 128 threads ----------------
__global__ void ln_kernel(const float* __restrict__ x,
                          const float* __restrict__ g,
                          const float* __restrict__ bta,
                          float* __restrict__ y) {
    int row = blockIdx.x;
    int tid = threadIdx.x;
    const float* xp = x + (size_t)row * E_;
    float v[3];
    float s = 0.f, sq = 0.f;
#pragma unroll
    for (int i = 0; i < 3; i++) {
        v[i] = xp[tid + i * 128];
        s  += v[i];
        sq += v[i] * v[i];
    }
    __shared__ float rs[4], rq[4];
#pragma unroll
    for (int off = 16; off; off >>= 1) {
        s  += __shfl_xor_sync(0xffffffffu, s,  off);
        sq += __shfl_xor_sync(0xffffffffu, sq, off);
    }
    if ((tid & 31) == 0) { rs[tid >> 5] = s; rq[tid >> 5] = sq; }
    __syncthreads();
    s  = rs[0] + rs[1] + rs[2] + rs[3];
    sq = rq[0] + rq[1] + rq[2] + rq[3];
    const float invE = 1.0f / E_;
    float mu  = s * invE;
    float var = sq * invE - mu * mu;
    float inv = rsqrtf(var + 1e-5f);
    float* yp = y + (size_t)row * E_;
#pragma unroll
    for (int i = 0; i < 3; i++) {
        int e = tid + i * 128;
        yp[e] = (v[i] - mu) * inv * g[e] + bta[e];
    }
}

// ---------------- generic tiled fp32 GEMM ----------------
// C[M,N] = (RESID ? resid : 0) + act(A[M,K] @ B[K,N] + (BIAS ? bias : 0))
// Assumes M % 64 == 0, K % 16 == 0 (true for all our shapes). N guarded.
template <bool RELU, bool RESID, bool BIAS>
__global__ void gemm64(const float* __restrict__ A, const float* __restrict__ Bm,
                       const float* __restrict__ bias, const float* __restrict__ resid,
                       float* __restrict__ C, int M, int N, int K) {
    constexpr int BM = 64, BN = 64, BK = 16;
    __shared__ float As[BK][BM + 1];
    __shared__ float Bs[BK][BN];
    int bm = blockIdx.y * BM;
    int bn = blockIdx.x * BN;
    int tid = threadIdx.x;          // 256 threads
    int tr = tid / 16, tc = tid % 16;
    float acc[4][4] = {};
    for (int k0 = 0; k0 < K; k0 += BK) {
#pragma unroll
        for (int i = 0; i < 4; i++) {
            int idx = tid + i * 256;
            int r = idx / BK, c = idx % BK;
            As[c][r] = A[(size_t)(bm + r) * K + k0 + c];
        }
#pragma unroll
        for (int i = 0; i < 4; i++) {
            int idx = tid + i * 256;
            int r = idx / BN, c = idx % BN;
            int n = bn + c;
            Bs[r][c] = (n < N) ? Bm[(size_t)(k0 + r) * N + n] : 0.f;
        }
        __syncthreads();
#pragma unroll
        for (int k = 0; k < BK; k++) {
            float ra[4], rb[4];
#pragma unroll
            for (int i = 0; i < 4; i++) ra[i] = As[k][tr * 4 + i];
#pragma unroll
            for (int j = 0; j < 4; j++) rb[j] = Bs[k][tc * 4 + j];
#pragma unroll
            for (int i = 0; i < 4; i++)
#pragma unroll
                for (int j = 0; j < 4; j++) acc[i][j] += ra[i] * rb[j];
        }
        __syncthreads();
    }
#pragma unroll
    for (int i = 0; i < 4; i++) {
        int m = bm + tr * 4 + i;
#pragma unroll
        for (int j = 0; j < 4; j++) {
            int n = bn + tc * 4 + j;
            if (n < N) {
                float v = acc[i][j];
                if (BIAS)  v += bias[n];
                if (RELU)  v = fmaxf(v, 0.f);
                if (RESID) v += resid[(size_t)m * N + n];
                C[(size_t)m * N + n] = v;
            }
        }
    }
}

// ---------------- fused causal attention ----------------
// One block per (b, h, t): scores over s<=t, softmax, o = p @ V.
__global__ void attn_kernel(const float* __restrict__ qkv, float* __restrict__ o) {
    const int tid = threadIdx.x;       // 128 threads
    int idx = blockIdx.x;              // b*H*T + h*T + t
    int t = idx & (T_ - 1);
    int h = (idx / T_) % H_;
    int b = idx / (T_ * H_);

    __shared__ float qs[HS_];
    __shared__ float p[T_];
    __shared__ float red[4];
    __shared__ float oacc[128];

    const float* base = qkv + (size_t)b * T_ * NQKV_;
    const float* qp = base + ((size_t)t * H_ + h) * QKV3_;
    if (tid < HS_) qs[tid] = qp[tid];
    __syncthreads();

    // scores
    for (int s = tid; s < T_; s += 128) {
        float sc = -INFINITY;
        if (s <= t) {
            const float* kp = base + ((size_t)s * H_ + h) * QKV3_ + HS_;
            float a = 0.f;
#pragma unroll
            for (int d = 0; d < HS_; d++) a += qs[d] * kp[d];
            sc = a * 0.125f;           // HS^-0.5
        }
        p[s] = sc;
    }
    __syncthreads();

    // max
    float m = fmaxf(p[tid], p[tid + 128]);
#pragma unroll
    for (int off = 16; off; off >>= 1) m = fmaxf(m, __shfl_xor_sync(0xffffffffu, m, off));
    if ((tid & 31) == 0) red[tid >> 5] = m;
    __syncthreads();
    m = fmaxf(fmaxf(red[0], red[1]), fmaxf(red[2], red[3]));

    // exp + sum
    float e0 = expf(p[tid] - m);
    float e1 = expf(p[tid + 128] - m);
    __syncthreads();                   // red reads done before rewrite
    p[tid] = e0;
    p[tid + 128] = e1;
    float ssum = e0 + e1;
#pragma unroll
    for (int off = 16; off; off >>= 1) ssum += __shfl_xor_sync(0xffffffffu, ssum, off);
    if ((tid & 31) == 0) red[tid >> 5] = ssum;
    __syncthreads();
    float inv = 1.0f / (red[0] + red[1] + red[2] + red[3]);

    // o = p @ V, split s over 2 thread groups per d
    int d = tid & 63, part = tid >> 6;
    float a = 0.f;
    for (int s = part; s <= t; s += 2)
        a += p[s] * base[((size_t)s * H_ + h) * QKV3_ + 2 * HS_ + d];
    oacc[tid] = a;
    __syncthreads();
    if (tid < 64)
        o[(size_t)(b * T_ + t) * E_ + h * HS_ + tid] = (oacc[tid] + oacc[tid + 64]) * inv;
}

// ---------------- host orchestration ----------------
extern "C" void kernel_launch(void* const* d_in, const int* in_sizes, int n_in,
                              void* d_out, int out_size) {
    const int*   context = (const int*)  d_in[0];
    const float* tok_emb = (const float*)d_in[1];
    const float* pos_emb = (const float*)d_in[2];
    const float* ln1_g   = (const float*)d_in[3];
    const float* ln1_b   = (const float*)d_in[4];
    const float* w_qkv   = (const float*)d_in[5];
    const float* w_proj  = (const float*)d_in[6];
    const float* b_proj  = (const float*)d_in[7];
    const float* ln2_g   = (const float*)d_in[8];
    const float* ln2_b   = (const float*)d_in[9];
    const float* w1      = (const float*)d_in[10];
    const float* b1      = (const float*)d_in[11];
    const float* w2      = (const float*)d_in[12];
    const float* b2      = (const float*)d_in[13];
    const float* lnf_g   = (const float*)d_in[14];
    const float* lnf_b   = (const float*)d_in[15];
    const float* w_head  = (const float*)d_in[16];
    const float* b_head  = (const float*)d_in[17];
    float* out = (float*)d_out;

    float *x, *xn, *qkv, *obuf, *ff, *wq;
    cudaGetSymbolAddress((void**)&x,    g_x);
    cudaGetSymbolAddress((void**)&xn,   g_xn);
    cudaGetSymbolAddress((void**)&qkv,  g_qkv);
    cudaGetSymbolAddress((void**)&obuf, g_obuf);
    cudaGetSymbolAddress((void**)&ff,   g_ff);
    cudaGetSymbolAddress((void**)&wq,   g_wq);

    // embedding
    {
        int tot = BT_ * E_;
        embed_kernel<<<(tot + 255) / 256, 256>>>(context, tok_emb, pos_emb, x);
    }
    // repack qkv weights
    {
        int tot = L_ * H_ * E_ * QKV3_;
        repack_kernel<<<(tot + 255) / 256, 256>>>(w_qkv, wq);
    }

    dim3 gemm_blk(256);
    for (int l = 0; l < L_; l++) {
        // LN1
        ln_kernel<<<BT_, 128>>>(x, ln1_g + l * E_, ln1_b + l * E_, xn);
        // QKV: [32768,384] x [384,1152]
        {
            dim3 grid(NQKV_ / 64, BT_ / 64);
            gemm64<false, false, false><<<grid, gemm_blk>>>(
                xn, wq + (size_t)l * E_ * NQKV_, nullptr, nullptr, qkv, BT_, NQKV_, E_);
        }
        // attention
        attn_kernel<<<B_ * H_ * T_, 128>>>(qkv, obuf);
        // proj + residual: x = x + obuf @ w_proj + b_proj
        {
            dim3 grid(E_ / 64, BT_ / 64);
            gemm64<false, true, true><<<grid, gemm_blk>>>(
                obuf, w_proj + (size_t)l * E_ * E_, b_proj + l * E_, x, x, BT_, E_, E_);
        }
        // LN2
        ln_kernel<<<BT_, 128>>>(x, ln2_g + l * E_, ln2_b + l * E_, xn);
        // FF1: relu(xn @ w1 + b1)
        {
            dim3 grid(FF_ / 64, BT_ / 64);
            gemm64<true, false, true><<<grid, gemm_blk>>>(
                xn, w1 + (size_t)l * E_ * FF_, b1 + l * FF_, nullptr, ff, BT_, FF_, E_);
        }
        // FF2 + residual: x = x + ff @ w2 + b2
        {
            dim3 grid(E_ / 64, BT_ / 64);
            gemm64<false, true, true><<<grid, gemm_blk>>>(
                ff, w2 + (size_t)l * FF_ * E_, b2 + l * E_, x, x, BT_, E_, FF_);
        }
    }
    // final LN
    ln_kernel<<<BT_, 128>>>(x, lnf_g, lnf_b, xn);
    // head: [32768,384] x [384,78]
    {
        dim3 grid((V_ + 63) / 64, BT_ / 64);
        gemm64<false, false, true><<<grid, gemm_blk>>>(
            xn, w_head, b_head, nullptr, out, BT_, V_, E_);
    }
}

// round 2
// speedup vs baseline: 3.1090x; 3.1090x over previous
#include <cuda_runtime.h>
#include <cuda_bf16.h>
#include <math.h>

// Problem constants
#define B_ 128
#define T_ 256
#define E_ 384
#define H_ 6
#define HS_ 64
#define L_ 6
#define V_ 78
#define FF_ 1536
#define QKV3_ 192           // 3*HS per head
#define NQKV_ (H_ * QKV3_)  // 1152

#define BT_ (B_ * T_)       // 32768

// ---------------- device scratch (static, no allocations) ----------------
__device__ float g_x   [BT_ * E_];
__device__ float g_xn  [BT_ * E_];
__device__ float g_qkv [BT_ * NQKV_];
__device__ float g_obuf[BT_ * E_];
__device__ float g_ff  [BT_ * FF_];
__device__ float g_wq  [L_ * E_ * NQKV_];

// ---------------- embedding ----------------
__global__ void embed_kernel(const int* __restrict__ ctx,
                             const float* __restrict__ tok,
                             const float* __restrict__ pos,
                             float* __restrict__ x) {
    int i = blockIdx.x * blockDim.x + threadIdx.x;
    if (i >= BT_ * E_) return;
    int e  = i % E_;
    int bt = i / E_;
    int t  = bt % T_;
    x[i] = tok[ctx[bt] * E_ + e] + pos[t * E_ + e];
}

// ---------------- repack w_qkv [L,H,E,192] -> [L,E,H*192] ----------------
__global__ void repack_kernel(const float* __restrict__ w, float* __restrict__ wp) {
    int i = blockIdx.x * blockDim.x + threadIdx.x;
    if (i >= L_ * H_ * E_ * QKV3_) return;
    int f = i % QKV3_;
    int e = (i / QKV3_) % E_;
    int h = (i / (QKV3_ * E_)) % H_;
    int l = i / (QKV3_ * E_ * H_);
    wp[((size_t)l * E_ + e) * NQKV_ + h * QKV3_ + f] = w[i];
}

// ---------------- layernorm: one block per token, 128 threads ----------------
__global__ void ln_kernel(const float* __restrict__ x,
                          const float* __restrict__ g,
                          const float* __restrict__ bta,
                          float* __restrict__ y) {
    int row = blockIdx.x;
    int tid = threadIdx.x;
    const float* xp = x + (size_t)row * E_;
    float v[3];
    float s = 0.f, sq = 0.f;
#pragma unroll
    for (int i = 0; i < 3; i++) {
        v[i] = xp[tid + i * 128];
        s  += v[i];
        sq += v[i] * v[i];
    }
    __shared__ float rs[4], rq[4];
#pragma unroll
    for (int off = 16; off; off >>= 1) {
        s  += __shfl_xor_sync(0xffffffffu, s,  off);
        sq += __shfl_xor_sync(0xffffffffu, sq, off);
    }
    if ((tid & 31) == 0) { rs[tid >> 5] = s; rq[tid >> 5] = sq; }
    __syncthreads();
    s  = rs[0] + rs[1] + rs[2] + rs[3];
    sq = rq[0] + rq[1] + rq[2] + rq[3];
    const float invE = 1.0f / E_;
    float mu  = s * invE;
    float var = sq * invE - mu * mu;
    float inv = rsqrtf(var + 1e-5f);
    float* yp = y + (size_t)row * E_;
#pragma unroll
    for (int i = 0; i < 3; i++) {
        int e = tid + i * 128;
        yp[e] = (v[i] - mu) * inv * g[e] + bta[e];
    }
}

// ---------------- big tiled fp32 GEMM: 128x128 tile, 8x8 micro ----------------
// Requires M%128==0, N%128==0, K%16==0.
template <bool RELU, bool RESID, bool BIAS>
__global__ __launch_bounds__(256, 2)
void gemm128(const float* __restrict__ A, const float* __restrict__ Bm,
             const float* __restrict__ bias, const float* __restrict__ resid,
             float* __restrict__ C, int M, int N, int K) {
    constexpr int BK = 16;
    __shared__ float As[BK][132];
    __shared__ float Bs[BK][128];
    int bm = blockIdx.y * 128;
    int bn = blockIdx.x * 128;
    int tid = threadIdx.x;
    int tr = tid >> 4, tc = tid & 15;
    float acc[8][8] = {};
    for (int k0 = 0; k0 < K; k0 += BK) {
#pragma unroll
        for (int u = 0; u < 2; u++) {
            int f4 = tid + u * 256;             // 0..511
            int r = f4 >> 2, cc = (f4 & 3) * 4;
            float4 av = *(const float4*)(A + (size_t)(bm + r) * K + k0 + cc);
            As[cc + 0][r] = av.x;
            As[cc + 1][r] = av.y;
            As[cc + 2][r] = av.z;
            As[cc + 3][r] = av.w;
        }
#pragma unroll
        for (int u = 0; u < 2; u++) {
            int f4 = tid + u * 256;
            int r = f4 >> 5, cc = (f4 & 31) * 4;
            *(float4*)&Bs[r][cc] = *(const float4*)(Bm + (size_t)(k0 + r) * N + bn + cc);
        }
        __syncthreads();
#pragma unroll
        for (int k = 0; k < BK; k++) {
            float4 a0 = *(float4*)&As[k][tr * 8];
            float4 a1 = *(float4*)&As[k][tr * 8 + 4];
            float4 b0 = *(float4*)&Bs[k][tc * 8];
            float4 b1 = *(float4*)&Bs[k][tc * 8 + 4];
            float ra[8] = {a0.x, a0.y, a0.z, a0.w, a1.x, a1.y, a1.z, a1.w};
            float rb[8] = {b0.x, b0.y, b0.z, b0.w, b1.x, b1.y, b1.z, b1.w};
#pragma unroll
            for (int i = 0; i < 8; i++)
#pragma unroll
                for (int j = 0; j < 8; j++) acc[i][j] += ra[i] * rb[j];
        }
        __syncthreads();
    }
#pragma unroll
    for (int i = 0; i < 8; i++) {
        int m = bm + tr * 8 + i;
#pragma unroll
        for (int j = 0; j < 8; j++) {
            int n = bn + tc * 8 + j;
            float v = acc[i][j];
            if (BIAS)  v += bias[n];
            if (RELU)  v = fmaxf(v, 0.f);
            if (RESID) v += resid[(size_t)m * N + n];
            C[(size_t)m * N + n] = v;
        }
    }
}

// ---------------- small GEMM for head (N=78) ----------------
template <bool RELU, bool RESID, bool BIAS>
__global__ void gemm64(const float* __restrict__ A, const float* __restrict__ Bm,
                       const float* __restrict__ bias, const float* __restrict__ resid,
                       float* __restrict__ C, int M, int N, int K) {
    constexpr int BM = 64, BN = 64, BK = 16;
    __shared__ float As[BK][BM + 1];
    __shared__ float Bs[BK][BN];
    int bm = blockIdx.y * BM;
    int bn = blockIdx.x * BN;
    int tid = threadIdx.x;
    int tr = tid / 16, tc = tid % 16;
    float acc[4][4] = {};
    for (int k0 = 0; k0 < K; k0 += BK) {
#pragma unroll
        for (int i = 0; i < 4; i++) {
            int idx = tid + i * 256;
            int r = idx / BK, c = idx % BK;
            As[c][r] = A[(size_t)(bm + r) * K + k0 + c];
        }
#pragma unroll
        for (int i = 0; i < 4; i++) {
            int idx = tid + i * 256;
            int r = idx / BN, c = idx % BN;
            int n = bn + c;
            Bs[r][c] = (n < N) ? Bm[(size_t)(k0 + r) * N + n] : 0.f;
        }
        __syncthreads();
#pragma unroll
        for (int k = 0; k < BK; k++) {
            float ra[4], rb[4];
#pragma unroll
            for (int i = 0; i < 4; i++) ra[i] = As[k][tr * 4 + i];
#pragma unroll
            for (int j = 0; j < 4; j++) rb[j] = Bs[k][tc * 4 + j];
#pragma unroll
            for (int i = 0; i < 4; i++)
#pragma unroll
                for (int j = 0; j < 4; j++) acc[i][j] += ra[i] * rb[j];
        }
        __syncthreads();
    }
#pragma unroll
    for (int i = 0; i < 4; i++) {
        int m = bm + tr * 4 + i;
#pragma unroll
        for (int j = 0; j < 4; j++) {
            int n = bn + tc * 4 + j;
            if (n < N) {
                float v = acc[i][j];
                if (BIAS)  v += bias[n];
                if (RELU)  v = fmaxf(v, 0.f);
                if (RESID) v += resid[(size_t)m * N + n];
                C[(size_t)m * N + n] = v;
            }
        }
    }
}

// ---------------- flash attention: block = (b, h, 64-row Q tile) ----------------
// smem layout (floats): Qs[64*65] Ks[64*65] Ss[64*65] Vs[64*64]
//                       part_m[256] part_s[256] m_s[64] l_s[64] alpha_s[64]
#define ATTN_SMEM_FLOATS (3 * 64 * 65 + 64 * 64 + 256 + 256 + 64 * 3)

__global__ __launch_bounds__(256)
void flash_attn(const float* __restrict__ qkv, float* __restrict__ o) {
    extern __shared__ float sm[];
    float* Qs      = sm;                   // stride 65
    float* Ks      = Qs + 64 * 65;         // stride 65
    float* Ss      = Ks + 64 * 65;         // stride 65
    float* Vs      = Ss + 64 * 65;         // stride 64
    float* part_m  = Vs + 64 * 64;
    float* part_s  = part_m + 256;
    float* m_s     = part_s + 256;
    float* l_s     = m_s + 64;
    float* alpha_s = l_s + 64;

    const int qt = blockIdx.x;   // 0..3
    const int h  = blockIdx.y;
    const int b  = blockIdx.z;
    const int tid = threadIdx.x; // 256
    const int tr = tid >> 4, tc = tid & 15;

    const float* base = qkv + (size_t)b * T_ * NQKV_ + h * QKV3_;

    // load Q tile
#pragma unroll
    for (int u = 0; u < 4; u++) {
        int f4 = tid + u * 256;          // 0..1023
        int r = f4 >> 4, c = (f4 & 15) * 4;
        float4 qv = *(const float4*)(base + (size_t)(qt * 64 + r) * NQKV_ + c);
        Qs[r * 65 + c + 0] = qv.x;
        Qs[r * 65 + c + 1] = qv.y;
        Qs[r * 65 + c + 2] = qv.z;
        Qs[r * 65 + c + 3] = qv.w;
    }
    if (tid < 64) { m_s[tid] = -1e30f; l_s[tid] = 0.f; }

    float acc[4][4] = {};

    for (int kt = 0; kt <= qt; kt++) {
        // load K,V tiles
#pragma unroll
        for (int u = 0; u < 4; u++) {
            int f4 = tid + u * 256;
            int r = f4 >> 4, c = (f4 & 15) * 4;
            const float* rowp = base + (size_t)(kt * 64 + r) * NQKV_;
            float4 kv = *(const float4*)(rowp + HS_ + c);
            Ks[r * 65 + c + 0] = kv.x;
            Ks[r * 65 + c + 1] = kv.y;
            Ks[r * 65 + c + 2] = kv.z;
            Ks[r * 65 + c + 3] = kv.w;
            *(float4*)&Vs[r * 64 + c] = *(const float4*)(rowp + 2 * HS_ + c);
        }
        __syncthreads();

        // S = Q @ K^T (4x4 per thread)
        float s4[4][4] = {};
#pragma unroll 8
        for (int d = 0; d < HS_; d++) {
            float ra[4], rb[4];
#pragma unroll
            for (int i = 0; i < 4; i++) ra[i] = Qs[(tr * 4 + i) * 65 + d];
#pragma unroll
            for (int j = 0; j < 4; j++) rb[j] = Ks[(tc * 4 + j) * 65 + d];
#pragma unroll
            for (int i = 0; i < 4; i++)
#pragma unroll
                for (int j = 0; j < 4; j++) s4[i][j] += ra[i] * rb[j];
        }
        const bool diag = (kt == qt);
#pragma unroll
        for (int i = 0; i < 4; i++) {
            int gi = tr * 4 + i;
#pragma unroll
            for (int j = 0; j < 4; j++) {
                int gj = tc * 4 + j;
                float v = s4[i][j] * 0.125f;
                if (diag && gj > gi) v = -1e30f;
                Ss[gi * 65 + gj] = v;
            }
        }
        __syncthreads();

        // online softmax row stats (4 threads per row, same warp)
        {
            int row = tid >> 2, seg = tid & 3, cb = seg * 16;
            float mx = -1e30f;
#pragma unroll
            for (int c = 0; c < 16; c++) mx = fmaxf(mx, Ss[row * 65 + cb + c]);
            part_m[tid] = mx;
            __syncwarp();
            float m_old = m_s[row];
            float m_new = fmaxf(fmaxf(part_m[row * 4 + 0], part_m[row * 4 + 1]),
                                fmaxf(part_m[row * 4 + 2], part_m[row * 4 + 3]));
            m_new = fmaxf(m_old, m_new);
            float ps = 0.f;
#pragma unroll
            for (int c = 0; c < 16; c++) {
                float p = __expf(Ss[row * 65 + cb + c] - m_new);
                Ss[row * 65 + cb + c] = p;
                ps += p;
            }
            part_s[tid] = ps;
            __syncwarp();
            if (seg == 0) {
                float alpha = __expf(m_old - m_new);
                alpha_s[row] = alpha;
                m_s[row] = m_new;
                l_s[row] = l_s[row] * alpha +
                           part_s[row * 4 + 0] + part_s[row * 4 + 1] +
                           part_s[row * 4 + 2] + part_s[row * 4 + 3];
            }
        }
        __syncthreads();

        // O = O*alpha + P @ V
        {
            float al[4];
#pragma unroll
            for (int i = 0; i < 4; i++) al[i] = alpha_s[tr * 4 + i];
#pragma unroll
            for (int i = 0; i < 4; i++)
#pragma unroll
                for (int j = 0; j < 4; j++) acc[i][j] *= al[i];
#pragma unroll 8
            for (int s = 0; s < 64; s++) {
                float4 bv = *(float4*)&Vs[s * 64 + tc * 4];
                float rb[4] = {bv.x, bv.y, bv.z, bv.w};
                float ra[4];
#pragma unroll
                for (int i = 0; i < 4; i++) ra[i] = Ss[(tr * 4 + i) * 65 + s];
#pragma unroll
                for (int i = 0; i < 4; i++)
#pragma unroll
                    for (int j = 0; j < 4; j++) acc[i][j] += ra[i] * rb[j];
            }
        }
        __syncthreads();
    }

    // write out o / l
#pragma unroll
    for (int i = 0; i < 4; i++) {
        int row = tr * 4 + i;
        float invl = 1.0f / l_s[row];
        int tglob = qt * 64 + row;
        float4 ov;
        ov.x = acc[i][0] * invl;
        ov.y = acc[i][1] * invl;
        ov.z = acc[i][2] * invl;
        ov.w = acc[i][3] * invl;
        *(float4*)(o + (size_t)(b * T_ + tglob) * E_ + h * HS_ + tc * 4) = ov;
    }
}

// ---------------- host orchestration ----------------
extern "C" void kernel_launch(void* const* d_in, const int* in_sizes, int n_in,
                              void* d_out, int out_size) {
    const int*   context = (const int*)  d_in[0];
    const float* tok_emb = (const float*)d_in[1];
    const float* pos_emb = (const float*)d_in[2];
    const float* ln1_g   = (const float*)d_in[3];
    const float* ln1_b   = (const float*)d_in[4];
    const float* w_qkv   = (const float*)d_in[5];
    const float* w_proj  = (const float*)d_in[6];
    const float* b_proj  = (const float*)d_in[7];
    const float* ln2_g   = (const float*)d_in[8];
    const float* ln2_b   = (const float*)d_in[9];
    const float* w1      = (const float*)d_in[10];
    const float* b1      = (const float*)d_in[11];
    const float* w2      = (const float*)d_in[12];
    const float* b2      = (const float*)d_in[13];
    const float* lnf_g   = (const float*)d_in[14];
    const float* lnf_b   = (const float*)d_in[15];
    const float* w_head  = (const float*)d_in[16];
    const float* b_head  = (const float*)d_in[17];
    float* out = (float*)d_out;

    float *x, *xn, *qkv, *obuf, *ff, *wq;
    cudaGetSymbolAddress((void**)&x,    g_x);
    cudaGetSymbolAddress((void**)&xn,   g_xn);
    cudaGetSymbolAddress((void**)&qkv,  g_qkv);
    cudaGetSymbolAddress((void**)&obuf, g_obuf);
    cudaGetSymbolAddress((void**)&ff,   g_ff);
    cudaGetSymbolAddress((void**)&wq,   g_wq);

    static bool attr_done = false;
    if (!attr_done) {
        cudaFuncSetAttribute(flash_attn, cudaFuncAttributeMaxDynamicSharedMemorySize,
                             ATTN_SMEM_FLOATS * 4);
        attr_done = true;
    }

    // embedding
    {
        int tot = BT_ * E_;
        embed_kernel<<<(tot + 255) / 256, 256>>>(context, tok_emb, pos_emb, x);
    }
    // repack qkv weights
    {
        int tot = L_ * H_ * E_ * QKV3_;
        repack_kernel<<<(tot + 255) / 256, 256>>>(w_qkv, wq);
    }

    for (int l = 0; l < L_; l++) {
        // LN1
        ln_kernel<<<BT_, 128>>>(x, ln1_g + l * E_, ln1_b + l * E_, xn);
        // QKV: [32768,384] x [384,1152]
        {
            dim3 grid(NQKV_ / 128, BT_ / 128);
            gemm128<false, false, false><<<grid, 256>>>(
                xn, wq + (size_t)l * E_ * NQKV_, nullptr, nullptr, qkv, BT_, NQKV_, E_);
        }
        // attention
        {
            dim3 grid(T_ / 64, H_, B_);
            flash_attn<<<grid, 256, ATTN_SMEM_FLOATS * 4>>>(qkv, obuf);
        }
        // proj + residual
        {
            dim3 grid(E_ / 128, BT_ / 128);
            gemm128<false, true, true><<<grid, 256>>>(
                obuf, w_proj + (size_t)l * E_ * E_, b_proj + l * E_, x, x, BT_, E_, E_);
        }
        // LN2
        ln_kernel<<<BT_, 128>>>(x, ln2_g + l * E_, ln2_b + l * E_, xn);
        // FF1
        {
            dim3 grid(FF_ / 128, BT_ / 128);
            gemm128<true, false, true><<<grid, 256>>>(
                xn, w1 + (size_t)l * E_ * FF_, b1 + l * FF_, nullptr, ff, BT_, FF_, E_);
        }
        // FF2 + residual
        {
            dim3 grid(E_ / 128, BT_ / 128);
            gemm128<false, true, true><<<grid, 256>>>(
                ff, w2 + (size_t)l * FF_ * E_, b2 + l * E_, x, x, BT_, E_, FF_);
        }
    }
    // final LN
    ln_kernel<<<BT_, 128>>>(x, lnf_g, lnf_b, xn);
    // head: [32768,384] x [384,78]
    {
        dim3 grid((V_ + 63) / 64, BT_ / 64);
        gemm64<false, false, true><<<grid, 256>>>(
            xn, w_head, b_head, nullptr, out, BT_, V_, E_);
    }
}

// round 4
// speedup vs baseline: 7.4184x; 2.3861x over previous
#include <cuda_runtime.h>
#include <cuda_bf16.h>
#include <math.h>
#include <stdint.h>

// Problem constants
#define B_ 128
#define T_ 256
#define E_ 384
#define H_ 6
#define HS_ 64
#define L_ 6
#define V_ 78
#define FF_ 1536
#define QKV3_ 192
#define NQKV_ (H_ * QKV3_)  // 1152
#define BT_ (B_ * T_)       // 32768

// ---------------- device scratch ----------------
__device__ float g_x   [BT_ * E_];
__device__ float g_xn  [BT_ * E_];
__device__ float g_qkv [BT_ * NQKV_];
__device__ float g_obuf[BT_ * E_];
__device__ float g_ff  [BT_ * FF_];
__device__ float g_wq  [L_ * E_ * NQKV_];

// ---------------- embedding ----------------
__global__ void embed_kernel(const int* __restrict__ ctx,
                             const float* __restrict__ tok,
                             const float* __restrict__ pos,
                             float* __restrict__ x) {
    int i = blockIdx.x * blockDim.x + threadIdx.x;
    if (i >= BT_ * E_) return;
    int e  = i % E_;
    int bt = i / E_;
    int t  = bt % T_;
    x[i] = tok[ctx[bt] * E_ + e] + pos[t * E_ + e];
}

// ---------------- repack w_qkv [L,H,E,192] -> [L,E,H*192] ----------------
__global__ void repack_kernel(const float* __restrict__ w, float* __restrict__ wp) {
    int i = blockIdx.x * blockDim.x + threadIdx.x;
    if (i >= L_ * H_ * E_ * QKV3_) return;
    int f = i % QKV3_;
    int e = (i / QKV3_) % E_;
    int h = (i / (QKV3_ * E_)) % H_;
    int l = i / (QKV3_ * E_ * H_);
    wp[((size_t)l * E_ + e) * NQKV_ + h * QKV3_ + f] = w[i];
}

// ---------------- layernorm ----------------
__global__ void ln_kernel(const float* __restrict__ x,
                          const float* __restrict__ g,
                          const float* __restrict__ bta,
                          float* __restrict__ y) {
    int row = blockIdx.x;
    int tid = threadIdx.x;
    const float* xp = x + (size_t)row * E_;
    float v[3];
    float s = 0.f, sq = 0.f;
#pragma unroll
    for (int i = 0; i < 3; i++) {
        v[i] = xp[tid + i * 128];
        s  += v[i];
        sq += v[i] * v[i];
    }
    __shared__ float rs[4], rq[4];
#pragma unroll
    for (int off = 16; off; off >>= 1) {
        s  += __shfl_xor_sync(0xffffffffu, s,  off);
        sq += __shfl_xor_sync(0xffffffffu, sq, off);
    }
    if ((tid & 31) == 0) { rs[tid >> 5] = s; rq[tid >> 5] = sq; }
    __syncthreads();
    s  = rs[0] + rs[1] + rs[2] + rs[3];
    sq = rq[0] + rq[1] + rq[2] + rq[3];
    const float invE = 1.0f / E_;
    float mu  = s * invE;
    float var = sq * invE - mu * mu;
    float inv = rsqrtf(var + 1e-5f);
    float* yp = y + (size_t)row * E_;
#pragma unroll
    for (int i = 0; i < 3; i++) {
        int e = tid + i * 128;
        yp[e] = (v[i] - mu) * inv * g[e] + bta[e];
    }
}

// ---------------- TF32 tensor-core GEMM: 128x128 tile, 8 warps, m16n8k8 ----------------
// Requires M%128==0, N%128==0, K%32==0.
__device__ __forceinline__ uint32_t f2tf32(float f) {
    uint32_t r;
    asm("cvt.rna.tf32.f32 %0, %1;" : "=r"(r) : "f"(f));
    return r;
}

template <bool RELU, bool RESID, bool BIAS>
__global__ __launch_bounds__(256, 2)
void gemm_tf32(const float* __restrict__ A, const float* __restrict__ Bm,
               const float* __restrict__ bias, const float* __restrict__ resid,
               float* __restrict__ C, int M, int N, int K) {
    __shared__ float As[128][36];   // m x k, pad 36
    __shared__ float Bs[32][136];   // k x n, pad 136
    const int tid  = threadIdx.x;
    const int wid  = tid >> 5, lane = tid & 31;
    const int gid  = lane >> 2, tig = lane & 3;
    const int wm   = wid & 1;       // 2 warps along m (64 each)
    const int wn   = wid >> 1;      // 4 warps along n (32 each)
    const int bm   = blockIdx.y * 128;
    const int bn   = blockIdx.x * 128;

    float c[4][4][4] = {};          // [mt][nt][reg]

    for (int k0 = 0; k0 < K; k0 += 32) {
        // A tile 128x32 = 1024 float4 (256 thr x 4 iters)
#pragma unroll
        for (int u = 0; u < 4; u++) {
            int f4 = tid + u * 256;             // 0..1023, 8 float4 per row
            int r = f4 >> 3, cc = (f4 & 7) * 4;
            float4 v = *(const float4*)(A + (size_t)(bm + r) * K + k0 + cc);
            As[r][cc + 0] = __uint_as_float(f2tf32(v.x));
            As[r][cc + 1] = __uint_as_float(f2tf32(v.y));
            As[r][cc + 2] = __uint_as_float(f2tf32(v.z));
            As[r][cc + 3] = __uint_as_float(f2tf32(v.w));
        }
        // B tile 32x128 = 1024 float4
#pragma unroll
        for (int u = 0; u < 4; u++) {
            int f4 = tid + u * 256;             // 32 float4 per row
            int r = f4 >> 5, cc = (f4 & 31) * 4;
            float4 v = *(const float4*)(Bm + (size_t)(k0 + r) * N + bn + cc);
            Bs[r][cc + 0] = __uint_as_float(f2tf32(v.x));
            Bs[r][cc + 1] = __uint_as_float(f2tf32(v.y));
            Bs[r][cc + 2] = __uint_as_float(f2tf32(v.z));
            Bs[r][cc + 3] = __uint_as_float(f2tf32(v.w));
        }
        __syncthreads();

#pragma unroll
        for (int kk = 0; kk < 4; kk++) {
            const int kb = kk * 8;
            uint32_t af[4][4], bf[4][2];
#pragma unroll
            for (int mt = 0; mt < 4; mt++) {
                int r0 = wm * 64 + mt * 16 + gid;
                af[mt][0] = __float_as_uint(As[r0    ][kb + tig]);
                af[mt][1] = __float_as_uint(As[r0 + 8][kb + tig]);
                af[mt][2] = __float_as_uint(As[r0    ][kb + tig + 4]);
                af[mt][3] = __float_as_uint(As[r0 + 8][kb + tig + 4]);
            }
#pragma unroll
            for (int nt = 0; nt < 4; nt++) {
                int cn = wn * 32 + nt * 8 + gid;
                bf[nt][0] = __float_as_uint(Bs[kb + tig    ][cn]);
                bf[nt][1] = __float_as_uint(Bs[kb + tig + 4][cn]);
            }
#pragma unroll
            for (int mt = 0; mt < 4; mt++)
#pragma unroll
                for (int nt = 0; nt < 4; nt++)
                    asm volatile(
                        "mma.sync.aligned.m16n8k8.row.col.f32.tf32.tf32.f32 "
                        "{%0,%1,%2,%3},{%4,%5,%6,%7},{%8,%9},{%0,%1,%2,%3};"
                        : "+f"(c[mt][nt][0]), "+f"(c[mt][nt][1]),
                          "+f"(c[mt][nt][2]), "+f"(c[mt][nt][3])
                        : "r"(af[mt][0]), "r"(af[mt][1]), "r"(af[mt][2]), "r"(af[mt][3]),
                          "r"(bf[nt][0]), "r"(bf[nt][1]));
        }
        __syncthreads();
    }

    // epilogue: c0,c1 -> (row, 2*tig), c2,c3 -> (row+8, 2*tig)
#pragma unroll
    for (int mt = 0; mt < 4; mt++) {
        int r0 = bm + wm * 64 + mt * 16 + gid;
#pragma unroll
        for (int nt = 0; nt < 4; nt++) {
            int cn = bn + wn * 32 + nt * 8 + tig * 2;
            float v0 = c[mt][nt][0], v1 = c[mt][nt][1];
            float v2 = c[mt][nt][2], v3 = c[mt][nt][3];
            if (BIAS) {
                float b0 = bias[cn], b1 = bias[cn + 1];
                v0 += b0; v1 += b1; v2 += b0; v3 += b1;
            }
            if (RELU) {
                v0 = fmaxf(v0, 0.f); v1 = fmaxf(v1, 0.f);
                v2 = fmaxf(v2, 0.f); v3 = fmaxf(v3, 0.f);
            }
            if (RESID) {
                const float2 ra = *(const float2*)(resid + (size_t)r0 * N + cn);
                const float2 rb = *(const float2*)(resid + (size_t)(r0 + 8) * N + cn);
                v0 += ra.x; v1 += ra.y; v2 += rb.x; v3 += rb.y;
            }
            *(float2*)(C + (size_t)r0 * N + cn)       = make_float2(v0, v1);
            *(float2*)(C + (size_t)(r0 + 8) * N + cn) = make_float2(v2, v3);
        }
    }
}

// ---------------- small GEMM for head (N=78), fp32 ----------------
template <bool RELU, bool RESID, bool BIAS>
__global__ void gemm64(const float* __restrict__ A, const float* __restrict__ Bm,
                       const float* __restrict__ bias, const float* __restrict__ resid,
                       float* __restrict__ C, int M, int N, int K) {
    constexpr int BM = 64, BN = 64, BK = 16;
    __shared__ float As[BK][BM + 1];
    __shared__ float Bs[BK][BN];
    int bm = blockIdx.y * BM;
    int bn = blockIdx.x * BN;
    int tid = threadIdx.x;
    int tr = tid / 16, tc = tid % 16;
    float acc[4][4] = {};
    for (int k0 = 0; k0 < K; k0 += BK) {
#pragma unroll
        for (int i = 0; i < 4; i++) {
            int idx = tid + i * 256;
            int r = idx / BK, c = idx % BK;
            As[c][r] = A[(size_t)(bm + r) * K + k0 + c];
        }
#pragma unroll
        for (int i = 0; i < 4; i++) {
            int idx = tid + i * 256;
            int r = idx / BN, c = idx % BN;
            int n = bn + c;
            Bs[r][c] = (n < N) ? Bm[(size_t)(k0 + r) * N + n] : 0.f;
        }
        __syncthreads();
#pragma unroll
        for (int k = 0; k < BK; k++) {
            float ra[4], rb[4];
#pragma unroll
            for (int i = 0; i < 4; i++) ra[i] = As[k][tr * 4 + i];
#pragma unroll
            for (int j = 0; j < 4; j++) rb[j] = Bs[k][tc * 4 + j];
#pragma unroll
            for (int i = 0; i < 4; i++)
#pragma unroll
                for (int j = 0; j < 4; j++) acc[i][j] += ra[i] * rb[j];
        }
        __syncthreads();
    }
#pragma unroll
    for (int i = 0; i < 4; i++) {
        int m = bm + tr * 4 + i;
#pragma unroll
        for (int j = 0; j < 4; j++) {
            int n = bn + tc * 4 + j;
            if (n < N) {
                float v = acc[i][j];
                if (BIAS)  v += bias[n];
                if (RELU)  v = fmaxf(v, 0.f);
                if (RESID) v += resid[(size_t)m * N + n];
                C[(size_t)m * N + n] = v;
            }
        }
    }
}

// ---------------- flash attention ----------------
#define ATTN_SMEM_FLOATS (3 * 64 * 65 + 64 * 64 + 256 + 256 + 64 * 3)

__global__ __launch_bounds__(256)
void flash_attn(const float* __restrict__ qkv, float* __restrict__ o) {
    extern __shared__ float sm[];
    float* Qs      = sm;
    float* Ks      = Qs + 64 * 65;
    float* Ss      = Ks + 64 * 65;
    float* Vs      = Ss + 64 * 65;
    float* part_m  = Vs + 64 * 64;
    float* part_s  = part_m + 256;
    float* m_s     = part_s + 256;
    float* l_s     = m_s + 64;
    float* alpha_s = l_s + 64;

    const int qt = blockIdx.x;
    const int h  = blockIdx.y;
    const int b  = blockIdx.z;
    const int tid = threadIdx.x;
    const int tr = tid >> 4, tc = tid & 15;

    const float* base = qkv + (size_t)b * T_ * NQKV_ + h * QKV3_;

#pragma unroll
    for (int u = 0; u < 4; u++) {
        int f4 = tid + u * 256;
        int r = f4 >> 4, c = (f4 & 15) * 4;
        float4 qv = *(const float4*)(base + (size_t)(qt * 64 + r) * NQKV_ + c);
        Qs[r * 65 + c + 0] = qv.x;
        Qs[r * 65 + c + 1] = qv.y;
        Qs[r * 65 + c + 2] = qv.z;
        Qs[r * 65 + c + 3] = qv.w;
    }
    if (tid < 64) { m_s[tid] = -1e30f; l_s[tid] = 0.f; }

    float acc[4][4] = {};

    for (int kt = 0; kt <= qt; kt++) {
#pragma unroll
        for (int u = 0; u < 4; u++) {
            int f4 = tid + u * 256;
            int r = f4 >> 4, c = (f4 & 15) * 4;
            const float* rowp = base + (size_t)(kt * 64 + r) * NQKV_;
            float4 kv = *(const float4*)(rowp + HS_ + c);
            Ks[r * 65 + c + 0] = kv.x;
            Ks[r * 65 + c + 1] = kv.y;
            Ks[r * 65 + c + 2] = kv.z;
            Ks[r * 65 + c + 3] = kv.w;
            *(float4*)&Vs[r * 64 + c] = *(const float4*)(rowp + 2 * HS_ + c);
        }
        __syncthreads();

        float s4[4][4] = {};
#pragma unroll 8
        for (int d = 0; d < HS_; d++) {
            float ra[4], rb[4];
#pragma unroll
            for (int i = 0; i < 4; i++) ra[i] = Qs[(tr * 4 + i) * 65 + d];
#pragma unroll
            for (int j = 0; j < 4; j++) rb[j] = Ks[(tc * 4 + j) * 65 + d];
#pragma unroll
            for (int i = 0; i < 4; i++)
#pragma unroll
                for (int j = 0; j < 4; j++) s4[i][j] += ra[i] * rb[j];
        }
        const bool diag = (kt == qt);
#pragma unroll
        for (int i = 0; i < 4; i++) {
            int gi = tr * 4 + i;
#pragma unroll
            for (int j = 0; j < 4; j++) {
                int gj = tc * 4 + j;
                float v = s4[i][j] * 0.125f;
                if (diag && gj > gi) v = -1e30f;
                Ss[gi * 65 + gj] = v;
            }
        }
        __syncthreads();

        {
            int row = tid >> 2, seg = tid & 3, cb = seg * 16;
            float mx = -1e30f;
#pragma unroll
            for (int c = 0; c < 16; c++) mx = fmaxf(mx, Ss[row * 65 + cb + c]);
            part_m[tid] = mx;
            __syncwarp();
            float m_old = m_s[row];
            float m_new = fmaxf(fmaxf(part_m[row * 4 + 0], part_m[row * 4 + 1]),
                                fmaxf(part_m[row * 4 + 2], part_m[row * 4 + 3]));
            m_new = fmaxf(m_old, m_new);
            float ps = 0.f;
#pragma unroll
            for (int c = 0; c < 16; c++) {
                float p = __expf(Ss[row * 65 + cb + c] - m_new);
                Ss[row * 65 + cb + c] = p;
                ps += p;
            }
            part_s[tid] = ps;
            __syncwarp();
            if (seg == 0) {
                float alpha = __expf(m_old - m_new);
                alpha_s[row] = alpha;
                m_s[row] = m_new;
                l_s[row] = l_s[row] * alpha +
                           part_s[row * 4 + 0] + part_s[row * 4 + 1] +
                           part_s[row * 4 + 2] + part_s[row * 4 + 3];
            }
        }
        __syncthreads();

        {
            float al[4];
#pragma unroll
            for (int i = 0; i < 4; i++) al[i] = alpha_s[tr * 4 + i];
#pragma unroll
            for (int i = 0; i < 4; i++)
#pragma unroll
                for (int j = 0; j < 4; j++) acc[i][j] *= al[i];
#pragma unroll 8
            for (int s = 0; s < 64; s++) {
                float4 bv = *(float4*)&Vs[s * 64 + tc * 4];
                float rb[4] = {bv.x, bv.y, bv.z, bv.w};
                float ra[4];
#pragma unroll
                for (int i = 0; i < 4; i++) ra[i] = Ss[(tr * 4 + i) * 65 + s];
#pragma unroll
                for (int i = 0; i < 4; i++)
#pragma unroll
                    for (int j = 0; j < 4; j++) acc[i][j] += ra[i] * rb[j];
            }
        }
        __syncthreads();
    }

#pragma unroll
    for (int i = 0; i < 4; i++) {
        int row = tr * 4 + i;
        float invl = 1.0f / l_s[row];
        int tglob = qt * 64 + row;
        float4 ov;
        ov.x = acc[i][0] * invl;
        ov.y = acc[i][1] * invl;
        ov.z = acc[i][2] * invl;
        ov.w = acc[i][3] * invl;
        *(float4*)(o + (size_t)(b * T_ + tglob) * E_ + h * HS_ + tc * 4) = ov;
    }
}

// ---------------- host orchestration ----------------
extern "C" void kernel_launch(void* const* d_in, const int* in_sizes, int n_in,
                              void* d_out, int out_size) {
    const int*   context = (const int*)  d_in[0];
    const float* tok_emb = (const float*)d_in[1];
    const float* pos_emb = (const float*)d_in[2];
    const float* ln1_g   = (const float*)d_in[3];
    const float* ln1_b   = (const float*)d_in[4];
    const float* w_qkv   = (const float*)d_in[5];
    const float* w_proj  = (const float*)d_in[6];
    const float* b_proj  = (const float*)d_in[7];
    const float* ln2_g   = (const float*)d_in[8];
    const float* ln2_b   = (const float*)d_in[9];
    const float* w1      = (const float*)d_in[10];
    const float* b1      = (const float*)d_in[11];
    const float* w2      = (const float*)d_in[12];
    const float* b2      = (const float*)d_in[13];
    const float* lnf_g   = (const float*)d_in[14];
    const float* lnf_b   = (const float*)d_in[15];
    const float* w_head  = (const float*)d_in[16];
    const float* b_head  = (const float*)d_in[17];
    float* out = (float*)d_out;

    float *x, *xn, *qkv, *obuf, *ff, *wq;
    cudaGetSymbolAddress((void**)&x,    g_x);
    cudaGetSymbolAddress((void**)&xn,   g_xn);
    cudaGetSymbolAddress((void**)&qkv,  g_qkv);
    cudaGetSymbolAddress((void**)&obuf, g_obuf);
    cudaGetSymbolAddress((void**)&ff,   g_ff);
    cudaGetSymbolAddress((void**)&wq,   g_wq);

    static bool attr_done = false;
    if (!attr_done) {
        cudaFuncSetAttribute(flash_attn, cudaFuncAttributeMaxDynamicSharedMemorySize,
                             ATTN_SMEM_FLOATS * 4);
        attr_done = true;
    }

    {
        int tot = BT_ * E_;
        embed_kernel<<<(tot + 255) / 256, 256>>>(context, tok_emb, pos_emb, x);
    }
    {
        int tot = L_ * H_ * E_ * QKV3_;
        repack_kernel<<<(tot + 255) / 256, 256>>>(w_qkv, wq);
    }

    for (int l = 0; l < L_; l++) {
        ln_kernel<<<BT_, 128>>>(x, ln1_g + l * E_, ln1_b + l * E_, xn);
        {
            dim3 grid(NQKV_ / 128, BT_ / 128);
            gemm_tf32<false, false, false><<<grid, 256>>>(
                xn, wq + (size_t)l * E_ * NQKV_, nullptr, nullptr, qkv, BT_, NQKV_, E_);
        }
        {
            dim3 grid(T_ / 64, H_, B_);
            flash_attn<<<grid, 256, ATTN_SMEM_FLOATS * 4>>>(qkv, obuf);
        }
        {
            dim3 grid(E_ / 128, BT_ / 128);
            gemm_tf32<false, true, true><<<grid, 256>>>(
                obuf, w_proj + (size_t)l * E_ * E_, b_proj + l * E_, x, x, BT_, E_, E_);
        }
        ln_kernel<<<BT_, 128>>>(x, ln2_g + l * E_, ln2_b + l * E_, xn);
        {
            dim3 grid(FF_ / 128, BT_ / 128);
            gemm_tf32<true, false, true><<<grid, 256>>>(
                xn, w1 + (size_t)l * E_ * FF_, b1 + l * FF_, nullptr, ff, BT_, FF_, E_);
        }
        {
            dim3 grid(E_ / 128, BT_ / 128);
            gemm_tf32<false, true, true><<<grid, 256>>>(
                ff, w2 + (size_t)l * FF_ * E_, b2 + l * E_, x, x, BT_, E_, FF_);
        }
    }
    ln_kernel<<<BT_, 128>>>(x, lnf_g, lnf_b, xn);
    {
        dim3 grid((V_ + 63) / 64, BT_ / 64);
        gemm64<false, false, true><<<grid, 256>>>(
            xn, w_head, b_head, nullptr, out, BT_, V_, E_);
    }
}